// round 12
// baseline (speedup 1.0000x reference)
#include <cuda_runtime.h>
#include <string.h>

// LearnableConvCensus: depthwise 3x3 conv (multiplier 8) -> sigmoid -> mean over 8.
// B=4, C=64, H=W=256, pad=1.
//
// sigmoid(z) = 0.5 + 0.5*tanh(z/2); fold 0.5*temperature[c] into pre-scaled
// weights/bias. out = 0.5 + (sum_m tanh_m) / 16.
//
// R12: rotating register window — each thread walks 16 CONSECUTIVE rows, so
// only ONE new window row is loaded per output row (3 LDS + 6 dup vs 12+18),
// prefetched into the just-freed buffer under the kh1/kh2 FMA shadow.
// Bias folded into the kh0 FFMA addend (no acc-init MOVs).

#define B_ 4
#define C_ 64
#define H_ 256
#define W_ 256
#define R_ 32                 // output rows per block
#define NROWS (R_ + 2)        // tile rows incl. halo
#define SROW 264              // smem row stride in floats

typedef unsigned long long ull;

__device__ __forceinline__ ull pack2(float lo, float hi) {
    ull r;
    asm("mov.b64 %0, {%1, %2};" : "=l"(r) : "f"(lo), "f"(hi));
    return r;
}
__device__ __forceinline__ ull dup2(float v) {
    ull r;
    asm("mov.b64 %0, {%1, %1};" : "=l"(r) : "f"(v));
    return r;
}
__device__ __forceinline__ void fma2(ull& acc, ull a, ull b) {
    asm("fma.rn.f32x2 %0, %1, %2, %0;" : "+l"(acc) : "l"(a), "l"(b));
}
__device__ __forceinline__ ull fma2v(ull a, ull b, ull c) {
    ull d;
    asm("fma.rn.f32x2 %0, %1, %2, %3;" : "=l"(d) : "l"(a), "l"(b), "l"(c));
    return d;
}
__device__ __forceinline__ float tanh_fast(float x) {
    float y;
    asm("tanh.approx.f32 %0, %1;" : "=f"(y) : "f"(x));
    return y;
}
// s += t via FFMA-imm (multiplier = immediate 1.0f -> rt_SMSP=1)
__device__ __forceinline__ void acc1(float& s, float t) {
    asm("fma.rn.f32 %0, %1, 0f3F800000, %0;" : "+f"(s) : "f"(t));
}

__global__ __launch_bounds__(128, 4)
void census_kernel(const float* __restrict__ x, const float* __restrict__ w,
                   const float* __restrict__ bias, const float* __restrict__ temp,
                   float* __restrict__ out) {
    __shared__ float      smem[NROWS * SROW];
    __shared__ ulonglong2 wsm2[9][2];   // [k][0]=(pair0,pair1), [k][1]=(pair2,pair3)
    __shared__ ull        bsm[4];

    const int bid   = blockIdx.x;
    const int strip = bid & 7;          // H_/R_ = 8 strips
    const int c     = (bid >> 3) & 63;
    const int b     = bid >> 9;
    const int h0    = strip * R_;
    const int tid   = threadIdx.x;

    const float* xp = x + ((size_t)(b * C_ + c) * H_) * W_;

    // ---- weight prep: w layout HWIO flattened w[(kh*3+kw)*512 + c*8 + m]
    if (tid < 40) {
        const float sc = 0.5f * __ldg(&temp[c]);
        if (tid < 36) {
            const int k = tid >> 2, p = tid & 3;
            const float w0 = __ldg(&w[k * 512 + (c << 3) + 2 * p])     * sc;
            const float w1 = __ldg(&w[k * 512 + (c << 3) + 2 * p + 1]) * sc;
            ((ull*)wsm2)[k * 4 + p] = pack2(w0, w1);
        } else {
            const int p = tid - 36;
            const float b0 = __ldg(&bias[(c << 3) + 2 * p])     * sc;
            const float b1 = __ldg(&bias[(c << 3) + 2 * p + 1]) * sc;
            bsm[p] = pack2(b0, b1);
        }
    }

    // ---- tile load: smem[r][4 + wcol] = x[h0 + r - 1][wcol]; cols 3 & 260 are
    // the zero conv padding (tiles span the full width).
    #pragma unroll
    for (int i = tid; i < NROWS * 64; i += 128) {
        const int r  = i >> 6;
        const int c4 = (i & 63) << 2;
        const int gh = h0 + r - 1;
        float4 v = make_float4(0.f, 0.f, 0.f, 0.f);
        if (gh >= 0 && gh < H_) v = *(const float4*)(xp + gh * W_ + c4);
        *(float4*)&smem[r * SROW + 4 + c4] = v;
    }
    for (int r = tid; r < NROWS; r += 128) {
        smem[r * SROW + 3]   = 0.f;
        smem[r * SROW + 260] = 0.f;
    }
    __syncthreads();

    const ull bp0 = bsm[0], bp1 = bsm[1], bp2 = bsm[2], bp3 = bsm[3];

    const int tx = tid & 63;   // 64 threads across width, 4 cols each
    const int ty = tid >> 6;   // 2 groups of 16 consecutive rows
    const int r0 = ty << 4;    // first output row of this thread (0 or 16)
    float* outp = out + (((size_t)(b * C_ + c) * H_) + h0 + r0) * W_ + (tx << 2);

    // load one smem row sr into a dup'd window buffer (3 LDS + 6 dup)
    auto loadrow = [&](int sr, ull* d) {
        const float* rowp = &smem[sr * SROW + (tx << 2)];
        const float  wm1 = rowp[3];
        const float4 f4  = *(const float4*)(rowp + 4);
        const float  wp4 = rowp[8];
        d[0] = dup2(wm1);
        d[1] = dup2(f4.x);
        d[2] = dup2(f4.y);
        d[3] = dup2(f4.z);
        d[4] = dup2(f4.w);
        d[5] = dup2(wp4);
    };

    // kh=0 taps, bias folded into the first FFMA addend
    auto tap0 = [&](const ull* d, ull acc[4][4]) {
        {
            const ulonglong2 w01 = wsm2[0][0];
            const ulonglong2 w23 = wsm2[0][1];
            #pragma unroll
            for (int j = 0; j < 4; j++) {
                acc[0][j] = fma2v(d[j], w01.x, bp0);
                acc[1][j] = fma2v(d[j], w01.y, bp1);
                acc[2][j] = fma2v(d[j], w23.x, bp2);
                acc[3][j] = fma2v(d[j], w23.y, bp3);
            }
        }
        #pragma unroll
        for (int kw = 1; kw < 3; kw++) {
            const ulonglong2 w01 = wsm2[kw][0];
            const ulonglong2 w23 = wsm2[kw][1];
            #pragma unroll
            for (int j = 0; j < 4; j++) {
                fma2(acc[0][j], d[j + kw], w01.x);
                fma2(acc[1][j], d[j + kw], w01.y);
                fma2(acc[2][j], d[j + kw], w23.x);
                fma2(acc[3][j], d[j + kw], w23.y);
            }
        }
    };

    auto tap = [&](int kh, const ull* d, ull acc[4][4]) {
        #pragma unroll
        for (int kw = 0; kw < 3; kw++) {
            const ulonglong2 w01 = wsm2[kh * 3 + kw][0];
            const ulonglong2 w23 = wsm2[kh * 3 + kw][1];
            #pragma unroll
            for (int j = 0; j < 4; j++) {
                fma2(acc[0][j], d[j + kw], w01.x);
                fma2(acc[1][j], d[j + kw], w01.y);
                fma2(acc[2][j], d[j + kw], w23.x);
                fma2(acc[3][j], d[j + kw], w23.y);
            }
        }
    };

    auto epi = [&](ull acc[4][4], int i) {
        float s[4] = {0.f, 0.f, 0.f, 0.f};
        #pragma unroll
        for (int p = 0; p < 4; p++) {
            #pragma unroll
            for (int j = 0; j < 4; j++) {
                float2 a;
                memcpy(&a, &acc[p][j], 8);
                acc1(s[j], tanh_fast(a.x));
                acc1(s[j], tanh_fast(a.y));
            }
        }
        float4 o;
        o.x = fmaf(s[0], 0.0625f, 0.5f);
        o.y = fmaf(s[1], 0.0625f, 0.5f);
        o.z = fmaf(s[2], 0.0625f, 0.5f);
        o.w = fmaf(s[3], 0.0625f, 0.5f);
        *(float4*)(outp + i * W_) = o;
    };

    // one output row: A=kh0 buffer (oldest), B=kh1, C=kh2.
    // After tap0 consumes A, prefetch the NEXT window row into A.
    auto rowstep = [&](ull* A, ull* B, ull* C, int i) {
        ull acc[4][4];
        tap0(A, acc);
        int sr = r0 + i + 3;                 // smem row for output row i+1's kh2
        if (sr > NROWS - 1) sr = NROWS - 1;  // last-iter dummy (in-bounds)
        loadrow(sr, A);
        tap(1, B, acc);
        tap(2, C, acc);
        epi(acc, i);
    };

    // prologue: output row r0 needs smem rows r0, r0+1, r0+2
    ull d0[6], d1[6], d2[6];
    loadrow(r0 + 0, d0);
    loadrow(r0 + 1, d1);
    loadrow(r0 + 2, d2);

    #pragma unroll 1
    for (int i = 0; i < 15; i += 3) {
        rowstep(d0, d1, d2, i);
        rowstep(d1, d2, d0, i + 1);
        rowstep(d2, d0, d1, i + 2);
    }
    rowstep(d0, d1, d2, 15);
}

extern "C" void kernel_launch(void* const* d_in, const int* in_sizes, int n_in,
                              void* d_out, int out_size) {
    const float* x    = (const float*)d_in[0];
    const float* w    = (const float*)d_in[1];
    const float* bias = (const float*)d_in[2];
    const float* temp = (const float*)d_in[3];
    float* out = (float*)d_out;

    const int grid = B_ * C_ * (H_ / R_);   // 4*64*8 = 2048 blocks
    census_kernel<<<grid, 128>>>(x, w, bias, temp, out);
}